// round 1
// baseline (speedup 1.0000x reference)
#include <cuda_runtime.h>
#include <cuda_bf16.h>

// Problem constants (fixed by the dataset)
#define NMAX 50000
#define EMAX 800000
#define GRAPHS 64

// Device scratch (allocation-free rule: __device__ globals)
static __device__ float g_h[NMAX * 128];    // layer input (post-relu)
static __device__ float g_hw[NMAX * 128];   // h @ W (pre-aggregation)
static __device__ float g_agg[NMAX * 128];  // aggregation target
static __device__ float g_dinv[NMAX];       // deg -> rsqrt(deg)
static __device__ float g_norm[EMAX];       // per-edge norm
static __device__ float g_psum[GRAPHS * 128];
static __device__ float g_pcnt[GRAPHS];

// ---------------- degree / norm ----------------

__global__ void k_deg_init(int n) {
    int i = blockIdx.x * blockDim.x + threadIdx.x;
    if (i < n) g_dinv[i] = 1.0f;  // self-loop contributes 1
}

__global__ void k_deg_edges(const int* __restrict__ dst, int E) {
    int e = blockIdx.x * blockDim.x + threadIdx.x;
    if (e < E) atomicAdd(&g_dinv[dst[e]], 1.0f);
}

__global__ void k_dinv(int n) {
    int i = blockIdx.x * blockDim.x + threadIdx.x;
    if (i < n) g_dinv[i] = rsqrtf(g_dinv[i]);
}

__global__ void k_zero_pool() {
    int i = blockIdx.x * blockDim.x + threadIdx.x;
    if (i < GRAPHS * 128) g_psum[i] = 0.0f;
    if (i < GRAPHS) g_pcnt[i] = 0.0f;
}

__global__ void k_norm(const int* __restrict__ src, const int* __restrict__ dst, int E) {
    int e = blockIdx.x * blockDim.x + threadIdx.x;
    if (e < E) g_norm[e] = g_dinv[src[e]] * g_dinv[dst[e]];
}

// ---------------- dense GEMM: g_hw = h @ W  ----------------
// Block of C threads handles 8 rows. W stays hot in L1/L2 (<=64KB).
template <int K, int C, bool FROMG>
__global__ void k_gemm(const float* __restrict__ hin, const float* __restrict__ W, int n) {
    __shared__ float sh[8][K];
    const float* __restrict__ h = FROMG ? (const float*)g_h : hin;
    int row0 = blockIdx.x * 8;
    for (int i = threadIdx.x; i < 8 * K; i += C) {
        int r = i / K, k = i - r * K;
        int row = row0 + r;
        sh[r][k] = (row < n) ? h[row * K + k] : 0.0f;
    }
    __syncthreads();
    int c = threadIdx.x;
#pragma unroll
    for (int r = 0; r < 8; r++) {
        int row = row0 + r;
        if (row >= n) return;
        float acc = 0.0f;
#pragma unroll
        for (int k = 0; k < K; k++) acc += sh[r][k] * W[k * C + c];
        g_hw[row * C + c] = acc;
    }
}

// ---------------- self-loop init: agg = hw * dinv^2 ----------------
template <int C>
__global__ void k_selfloop(int n) {
    int idx = blockIdx.x * blockDim.x + threadIdx.x;
    if (idx < n * C) {
        float d = g_dinv[idx / C];
        g_agg[idx] = g_hw[idx] * (d * d);
    }
}

// ---------------- edge scatter: agg[dst] += hw[src] * norm ----------------
template <int C, int EPB>
__global__ void k_scatter(const int* __restrict__ src, const int* __restrict__ dst, int E) {
    int c = threadIdx.x;
    int e0 = blockIdx.x * EPB;
#pragma unroll
    for (int i = 0; i < EPB; i++) {
        int e = e0 + i;
        if (e >= E) return;
        int s = __ldg(&src[e]);
        int d = __ldg(&dst[e]);
        float nm = __ldg(&g_norm[e]);
        atomicAdd(&g_agg[d * C + c], g_hw[s * C + c] * nm);
    }
}

// ---------------- epilogue: h = relu(agg + b) ----------------
template <int C>
__global__ void k_bias_relu(const float* __restrict__ b, int n) {
    int idx = blockIdx.x * blockDim.x + threadIdx.x;
    if (idx < n * C) {
        int c = idx & (C - 1);
        g_h[idx] = fmaxf(g_agg[idx] + __ldg(&b[c]), 0.0f);
    }
}

// ---------------- mean pool over sorted batch ----------------
// Each block: 256 nodes, 128 channel-threads. Register-accumulate per segment
// run, flush with atomics only on graph-id change (batch is sorted).
__global__ void k_pool(const int* __restrict__ batch, int n) {
    const int NPB = 256;
    int c = threadIdx.x;  // 128 threads
    int i0 = blockIdx.x * NPB;
    int cur = -1, cnt = 0;
    float acc = 0.0f;
    for (int j = 0; j < NPB; j++) {
        int i = i0 + j;
        if (i >= n) break;
        int g = __ldg(&batch[i]);
        if (g != cur) {
            if (cur >= 0) {
                atomicAdd(&g_psum[cur * 128 + c], acc);
                if (c == 0) atomicAdd(&g_pcnt[cur], (float)cnt);
            }
            cur = g; acc = 0.0f; cnt = 0;
        }
        acc += g_h[i * 128 + c];
        cnt++;
    }
    if (cur >= 0) {
        atomicAdd(&g_psum[cur * 128 + c], acc);
        if (c == 0) atomicAdd(&g_pcnt[cur], (float)cnt);
    }
}

// ---------------- MLP head: one block per graph ----------------
__global__ void k_fc(const float* __restrict__ Wf1, const float* __restrict__ bf1,
                     const float* __restrict__ Wf2, const float* __restrict__ bf2,
                     float* __restrict__ out) {
    int g = blockIdx.x;
    int t = threadIdx.x;  // 128
    __shared__ float p[128];
    __shared__ float f1[64];
    float inv = 1.0f / fmaxf(g_pcnt[g], 1.0f);
    p[t] = g_psum[g * 128 + t] * inv;
    __syncthreads();
    if (t < 64) {
        float acc = bf1[t];
#pragma unroll
        for (int k = 0; k < 128; k++) acc += p[k] * Wf1[k * 64 + t];
        f1[t] = fmaxf(acc, 0.0f);
    }
    __syncthreads();
    if (t < 10) {
        float acc = bf2[t];
#pragma unroll
        for (int k = 0; k < 64; k++) acc += f1[k] * Wf2[k * 10 + t];
        out[g * 10 + t] = acc;
    }
}

extern "C" void kernel_launch(void* const* d_in, const int* in_sizes, int n_in,
                              void* d_out, int out_size) {
    const float* x   = (const float*)d_in[0];
    const int* ei    = (const int*)d_in[1];
    const int* batch = (const int*)d_in[2];
    const float* W1  = (const float*)d_in[3];
    const float* b1  = (const float*)d_in[4];
    const float* W2  = (const float*)d_in[5];
    const float* b2  = (const float*)d_in[6];
    const float* W3  = (const float*)d_in[7];
    const float* b3  = (const float*)d_in[8];
    const float* Wf1 = (const float*)d_in[9];
    const float* bf1 = (const float*)d_in[10];
    const float* Wf2 = (const float*)d_in[11];
    const float* bf2 = (const float*)d_in[12];
    float* out = (float*)d_out;

    int N = in_sizes[0] / 3;
    int E = in_sizes[1] / 2;
    const int* src = ei;
    const int* dst = ei + E;

    // degree / dinv / norm
    k_deg_init<<<(N + 255) / 256, 256>>>(N);
    k_deg_edges<<<(E + 255) / 256, 256>>>(dst, E);
    k_dinv<<<(N + 255) / 256, 256>>>(N);
    k_zero_pool<<<(GRAPHS * 128 + 255) / 256, 256>>>();
    k_norm<<<(E + 255) / 256, 256>>>(src, dst, E);

    // Layer 1: 3 -> 64
    k_gemm<3, 64, false><<<(N + 7) / 8, 64>>>(x, W1, N);
    k_selfloop<64><<<(N * 64 + 255) / 256, 256>>>(N);
    k_scatter<64, 4><<<(E + 3) / 4, 64>>>(src, dst, E);
    k_bias_relu<64><<<(N * 64 + 255) / 256, 256>>>(b1, N);

    // Layer 2: 64 -> 128
    k_gemm<64, 128, true><<<(N + 7) / 8, 128>>>(nullptr, W2, N);
    k_selfloop<128><<<(N * 128 + 255) / 256, 256>>>(N);
    k_scatter<128, 4><<<(E + 3) / 4, 128>>>(src, dst, E);
    k_bias_relu<128><<<(N * 128 + 255) / 256, 256>>>(b2, N);

    // Layer 3: 128 -> 128
    k_gemm<128, 128, true><<<(N + 7) / 8, 128>>>(nullptr, W3, N);
    k_selfloop<128><<<(N * 128 + 255) / 256, 256>>>(N);
    k_scatter<128, 4><<<(E + 3) / 4, 128>>>(src, dst, E);
    k_bias_relu<128><<<(N * 128 + 255) / 256, 256>>>(b3, N);

    // Pool + head
    k_pool<<<(N + 255) / 256, 128>>>(batch, N);
    k_fc<<<GRAPHS, 128>>>(Wf1, bf1, Wf2, bf2, out);
}

// round 2
// speedup vs baseline: 2.3804x; 2.3804x over previous
#include <cuda_runtime.h>
#include <cuda_bf16.h>

#define NMAX 50000
#define EMAX 800000
#define GRAPHS 64

// ---------------- device scratch (allocation-free rule) ----------------
static __device__ float g_h[NMAX * 128];    // features (post-activation)
static __device__ float g_a[NMAX * 128];    // aggregated features
static __device__ float g_dinv[NMAX];
static __device__ int   g_cnt[NMAX];        // in-degree (no self loop)
static __device__ int   g_rowptr[NMAX + 1];
static __device__ int   g_cursor[NMAX];
static __device__ int   g_esrc[EMAX];       // CSR src, grouped by dst
static __device__ float g_enorm[EMAX];      // per-edge norm, same order
static __device__ float g_psum[GRAPHS * 128];
static __device__ float g_pcnt[GRAPHS];

typedef unsigned long long ull;

// ---------------- f32x2 helpers ----------------
__device__ __forceinline__ ull pack2(float x, float y) {
    ull r; asm("mov.b64 %0, {%1,%2};" : "=l"(r) : "f"(x), "f"(y)); return r;
}
__device__ __forceinline__ void unpack2(ull v, float& x, float& y) {
    asm("mov.b64 {%0,%1}, %2;" : "=f"(x), "=f"(y) : "l"(v));
}
__device__ __forceinline__ ull ffma2(ull a, ull b, ull c) {
    ull d; asm("fma.rn.f32x2 %0, %1, %2, %3;" : "=l"(d) : "l"(a), "l"(b), "l"(c));
    return d;
}

// ---------------- prep ----------------
__global__ void k_init(int n) {
    int i = blockIdx.x * blockDim.x + threadIdx.x;
    if (i < n) { g_cnt[i] = 0; g_cursor[i] = 0; }
    if (i < GRAPHS * 128) g_psum[i] = 0.0f;
    if (i < GRAPHS) g_pcnt[i] = 0.0f;
}

__global__ void k_count(const int* __restrict__ dst, int E) {
    int e = blockIdx.x * blockDim.x + threadIdx.x;
    if (e < E) atomicAdd(&g_cnt[dst[e]], 1);
}

__global__ void k_dinv(int n) {
    int i = blockIdx.x * blockDim.x + threadIdx.x;
    if (i < n) g_dinv[i] = rsqrtf((float)g_cnt[i] + 1.0f);
}

// single-block exclusive scan of g_cnt -> g_rowptr (shfl-based)
__global__ void k_scan(int n, int E) {
    __shared__ int swarp[32];
    __shared__ int scarry;
    int t = threadIdx.x;            // 1024 threads
    int lane = t & 31, wid = t >> 5;
    if (t == 0) scarry = 0;
    __syncthreads();
    for (int base = 0; base < n; base += 1024) {
        int i = base + t;
        int v = (i < n) ? g_cnt[i] : 0;
        int c = scarry;
        // warp inclusive scan
        int incl = v;
#pragma unroll
        for (int off = 1; off < 32; off <<= 1) {
            int y = __shfl_up_sync(0xffffffffu, incl, off);
            if (lane >= off) incl += y;
        }
        if (lane == 31) swarp[wid] = incl;
        __syncthreads();
        if (wid == 0) {
            int w = swarp[lane];
            int wi = w;
#pragma unroll
            for (int off = 1; off < 32; off <<= 1) {
                int y = __shfl_up_sync(0xffffffffu, wi, off);
                if (lane >= off) wi += y;
            }
            swarp[lane] = wi;
        }
        __syncthreads();
        int woff = (wid > 0) ? swarp[wid - 1] : 0;
        incl += woff;
        if (i < n) g_rowptr[i] = c + incl - v;
        int total = swarp[31];
        __syncthreads();
        if (t == 0) scarry = c + total;
        __syncthreads();
    }
    if (t == 0) g_rowptr[n] = E;
}

__global__ void k_fill(const int* __restrict__ src, const int* __restrict__ dst, int E) {
    int e = blockIdx.x * blockDim.x + threadIdx.x;
    if (e < E) {
        int s = src[e], d = dst[e];
        int pos = g_rowptr[d] + atomicAdd(&g_cursor[d], 1);
        g_esrc[pos] = s;
        g_enorm[pos] = g_dinv[s] * g_dinv[d];
    }
}

// ---------------- aggregation (pull, CSR) ----------------
// C=3 special: thread per node
__global__ void k_agg3(const float* __restrict__ x, int n) {
    int i = blockIdx.x * blockDim.x + threadIdx.x;
    if (i >= n) return;
    int beg = g_rowptr[i], end = g_rowptr[i + 1];
    float di = g_dinv[i];
    float w0 = di * di;
    float a0 = x[i * 3 + 0] * w0, a1 = x[i * 3 + 1] * w0, a2 = x[i * 3 + 2] * w0;
    for (int j = beg; j < end; j++) {
        int s = g_esrc[j];
        float w = g_enorm[j];
        a0 += x[s * 3 + 0] * w;
        a1 += x[s * 3 + 1] * w;
        a2 += x[s * 3 + 2] * w;
    }
    g_a[i * 3 + 0] = a0; g_a[i * 3 + 1] = a1; g_a[i * 3 + 2] = a2;
}

// warp per node; VPL floats per lane (C = 32*VPL), vectorized loads
template <int VPL>
__global__ void k_agg(int n) {
    const int C = 32 * VPL;
    int warp = (blockIdx.x * blockDim.x + threadIdx.x) >> 5;
    int lane = threadIdx.x & 31;
    if (warp >= n) return;
    int i = warp;
    int beg = g_rowptr[i], end = g_rowptr[i + 1];
    float di = g_dinv[i];
    float sw = di * di;
    float acc[VPL];
    const float* __restrict__ hp = g_h;
#pragma unroll
    for (int v = 0; v < VPL; v++) acc[v] = hp[i * C + lane * VPL + v] * sw;

    int j = beg;
    for (; j + 4 <= end; j += 4) {
        int s0 = g_esrc[j], s1 = g_esrc[j + 1], s2 = g_esrc[j + 2], s3 = g_esrc[j + 3];
        float w0 = g_enorm[j], w1 = g_enorm[j + 1], w2 = g_enorm[j + 2], w3 = g_enorm[j + 3];
        if (VPL == 4) {
            float4 v0 = *(const float4*)&hp[s0 * C + lane * 4];
            float4 v1 = *(const float4*)&hp[s1 * C + lane * 4];
            float4 v2 = *(const float4*)&hp[s2 * C + lane * 4];
            float4 v3 = *(const float4*)&hp[s3 * C + lane * 4];
            acc[0] += v0.x * w0 + v1.x * w1 + v2.x * w2 + v3.x * w3;
            acc[1] += v0.y * w0 + v1.y * w1 + v2.y * w2 + v3.y * w3;
            acc[2] += v0.z * w0 + v1.z * w1 + v2.z * w2 + v3.z * w3;
            acc[3] += v0.w * w0 + v1.w * w1 + v2.w * w2 + v3.w * w3;
        } else {
            float2 v0 = *(const float2*)&hp[s0 * C + lane * 2];
            float2 v1 = *(const float2*)&hp[s1 * C + lane * 2];
            float2 v2 = *(const float2*)&hp[s2 * C + lane * 2];
            float2 v3 = *(const float2*)&hp[s3 * C + lane * 2];
            acc[0] += v0.x * w0 + v1.x * w1 + v2.x * w2 + v3.x * w3;
            acc[1] += v0.y * w0 + v1.y * w1 + v2.y * w2 + v3.y * w3;
        }
    }
    for (; j < end; j++) {
        int s = g_esrc[j];
        float w = g_enorm[j];
        if (VPL == 4) {
            float4 v = *(const float4*)&hp[s * C + lane * 4];
            acc[0] += v.x * w; acc[1] += v.y * w; acc[2] += v.z * w; acc[3] += v.w * w;
        } else {
            float2 v = *(const float2*)&hp[s * C + lane * 2];
            acc[0] += v.x * w; acc[1] += v.y * w;
        }
    }
    if (VPL == 4) {
        float4 o; o.x = acc[0]; o.y = acc[1]; o.z = acc[2]; o.w = acc[3];
        *(float4*)&g_a[i * C + lane * 4] = o;
    } else {
        float2 o; o.x = acc[0]; o.y = acc[1];
        *(float2*)&g_a[i * C + lane * 2] = o;
    }
}

// ---------------- GEMM + bias + relu:  g_h = relu(g_a @ W + b) ----------------
// K=3 special (layer 1): one thread per output element
__global__ void k_gemm3(const float* __restrict__ W, const float* __restrict__ b, int n) {
    int idx = blockIdx.x * blockDim.x + threadIdx.x;
    if (idx >= n * 64) return;
    int row = idx >> 6, c = idx & 63;
    float a0 = g_a[row * 3 + 0], a1 = g_a[row * 3 + 1], a2 = g_a[row * 3 + 2];
    float acc = b[c] + a0 * W[c] + a1 * W[64 + c] + a2 * W[128 + c];
    g_h[row * 64 + c] = fmaxf(acc, 0.0f);
}

// K in {64,128}, C=128. Block: dim3(64,2) = 128 thr. ROWS=16 rows/block,
// each thread: 8 rows x 2 channels, f32x2 accumulators.
template <int K>
__global__ void k_gemm(const float* __restrict__ W, const float* __restrict__ b, int n) {
    const int C = 128, ROWS = 16, RPT = 8;
    __shared__ float sh[ROWS][K];
    int tc = threadIdx.x;            // 0..63 -> channels 2tc, 2tc+1
    int ty = threadIdx.y;            // 0..1
    int tid = ty * 64 + tc;
    int row0 = blockIdx.x * ROWS;

    // cooperative load of ROWS x K activations (float4)
    const int NV = ROWS * K / 4;
    for (int v = tid; v < NV; v += 128) {
        int o = v * 4;
        int r = o / K, k = o - r * K;
        int row = row0 + r;
        float4 val = (row < n) ? *(const float4*)&g_a[row * K + k]
                               : make_float4(0.f, 0.f, 0.f, 0.f);
        *(float4*)&sh[r][k] = val;
    }
    __syncthreads();

    const ull* __restrict__ Wll = (const ull*)W;
    ull acc[RPT];
    {
        float2 bb = *(const float2*)&b[2 * tc];
        ull binit = pack2(bb.x, bb.y);
#pragma unroll
        for (int r = 0; r < RPT; r++) acc[r] = binit;
    }
    int rbase = ty * RPT;
#pragma unroll 4
    for (int k = 0; k < K; k += 2) {
        ull w0 = Wll[k * (C / 2) + tc];
        ull w1 = Wll[(k + 1) * (C / 2) + tc];
#pragma unroll
        for (int r = 0; r < RPT; r++) {
            float2 s2 = *(const float2*)&sh[rbase + r][k];
            acc[r] = ffma2(pack2(s2.x, s2.x), w0, acc[r]);
            acc[r] = ffma2(pack2(s2.y, s2.y), w1, acc[r]);
        }
    }
#pragma unroll
    for (int r = 0; r < RPT; r++) {
        int row = row0 + rbase + r;
        if (row < n) {
            float x, y; unpack2(acc[r], x, y);
            float2 o; o.x = fmaxf(x, 0.0f); o.y = fmaxf(y, 0.0f);
            *(float2*)&g_h[row * C + 2 * tc] = o;
        }
    }
}

// ---------------- mean pool over sorted batch ----------------
__global__ void k_pool(const int* __restrict__ batch, int n) {
    const int NPB = 256;
    int c = threadIdx.x;  // 128 threads
    int i0 = blockIdx.x * NPB;
    int cur = -1, cnt = 0;
    float acc = 0.0f;
    for (int j = 0; j < NPB; j++) {
        int i = i0 + j;
        if (i >= n) break;
        int g = __ldg(&batch[i]);
        if (g != cur) {
            if (cur >= 0) {
                atomicAdd(&g_psum[cur * 128 + c], acc);
                if (c == 0) atomicAdd(&g_pcnt[cur], (float)cnt);
            }
            cur = g; acc = 0.0f; cnt = 0;
        }
        acc += g_h[i * 128 + c];
        cnt++;
    }
    if (cur >= 0) {
        atomicAdd(&g_psum[cur * 128 + c], acc);
        if (c == 0) atomicAdd(&g_pcnt[cur], (float)cnt);
    }
}

// ---------------- MLP head ----------------
__global__ void k_fc(const float* __restrict__ Wf1, const float* __restrict__ bf1,
                     const float* __restrict__ Wf2, const float* __restrict__ bf2,
                     float* __restrict__ out) {
    int g = blockIdx.x;
    int t = threadIdx.x;  // 128
    __shared__ float p[128];
    __shared__ float f1[64];
    float inv = 1.0f / fmaxf(g_pcnt[g], 1.0f);
    p[t] = g_psum[g * 128 + t] * inv;
    __syncthreads();
    if (t < 64) {
        float acc = bf1[t];
#pragma unroll
        for (int k = 0; k < 128; k++) acc += p[k] * Wf1[k * 64 + t];
        f1[t] = fmaxf(acc, 0.0f);
    }
    __syncthreads();
    if (t < 10) {
        float acc = bf2[t];
#pragma unroll
        for (int k = 0; k < 64; k++) acc += f1[k] * Wf2[k * 10 + t];
        out[g * 10 + t] = acc;
    }
}

extern "C" void kernel_launch(void* const* d_in, const int* in_sizes, int n_in,
                              void* d_out, int out_size) {
    const float* x   = (const float*)d_in[0];
    const int* ei    = (const int*)d_in[1];
    const int* batch = (const int*)d_in[2];
    const float* W1  = (const float*)d_in[3];
    const float* b1  = (const float*)d_in[4];
    const float* W2  = (const float*)d_in[5];
    const float* b2  = (const float*)d_in[6];
    const float* W3  = (const float*)d_in[7];
    const float* b3  = (const float*)d_in[8];
    const float* Wf1 = (const float*)d_in[9];
    const float* bf1 = (const float*)d_in[10];
    const float* Wf2 = (const float*)d_in[11];
    const float* bf2 = (const float*)d_in[12];
    float* out = (float*)d_out;

    int N = in_sizes[0] / 3;
    int E = in_sizes[1] / 2;
    const int* src = ei;
    const int* dst = ei + E;

    // CSR + norms (once per launch, reused by all 3 layers)
    k_init<<<(N + 255) / 256, 256>>>(N);
    k_count<<<(E + 255) / 256, 256>>>(dst, E);
    k_dinv<<<(N + 255) / 256, 256>>>(N);
    k_scan<<<1, 1024>>>(N, E);
    k_fill<<<(E + 255) / 256, 256>>>(src, dst, E);

    // Layer 1: aggregate at C=3, then 3->64 transform
    k_agg3<<<(N + 127) / 128, 128>>>(x, N);
    k_gemm3<<<(N * 64 + 255) / 256, 256>>>(W1, b1, N);

    // Layer 2: aggregate at C=64, then 64->128
    k_agg<2><<<(N + 7) / 8, 256>>>(N);
    k_gemm<64><<<(N + 15) / 16, dim3(64, 2)>>>(W2, b2, N);

    // Layer 3: aggregate at C=128, then 128->128
    k_agg<4><<<(N + 7) / 8, 256>>>(N);
    k_gemm<128><<<(N + 15) / 16, dim3(64, 2)>>>(W3, b3, N);

    // Pool + head
    k_pool<<<(N + 255) / 256, 128>>>(batch, N);
    k_fc<<<GRAPHS, 128>>>(Wf1, bf1, Wf2, bf2, out);
}

// round 3
// speedup vs baseline: 2.6275x; 1.1038x over previous
#include <cuda_runtime.h>
#include <cuda_bf16.h>

#define NMAX 50000
#define EMAX 800000
#define GRAPHS 64
#define SCAN_B 1024

// ---------------- device scratch (allocation-free rule) ----------------
static __device__ float g_h[NMAX * 128];    // features (post-activation)
static __device__ float g_a[NMAX * 128];    // aggregated features
static __device__ float g_dinv[NMAX];
static __device__ int   g_cnt[NMAX];        // in-degree (no self loop)
static __device__ int   g_rowptr[NMAX + 1];
static __device__ int   g_cursor[NMAX];
static __device__ int   g_bsum[64];         // per-block scan totals
static __device__ int   g_esrc[EMAX];       // CSR src, grouped by dst
static __device__ float g_enorm[EMAX];      // per-edge norm, same order
static __device__ float g_psum[GRAPHS * 128];
static __device__ float g_pcnt[GRAPHS];

typedef unsigned long long ull;

// ---------------- f32x2 helpers ----------------
__device__ __forceinline__ ull pack2(float x, float y) {
    ull r; asm("mov.b64 %0, {%1,%2};" : "=l"(r) : "f"(x), "f"(y)); return r;
}
__device__ __forceinline__ void unpack2(ull v, float& x, float& y) {
    asm("mov.b64 {%0,%1}, %2;" : "=f"(x), "=f"(y) : "l"(v));
}
__device__ __forceinline__ ull ffma2(ull a, ull b, ull c) {
    ull d; asm("fma.rn.f32x2 %0, %1, %2, %3;" : "=l"(d) : "l"(a), "l"(b), "l"(c));
    return d;
}

// ---------------- prep ----------------
__global__ void k_zero(int n) {
    int i = blockIdx.x * blockDim.x + threadIdx.x;
    if (i < n) g_cnt[i] = 0;
    if (i < GRAPHS * 128) g_psum[i] = 0.0f;
    if (i < GRAPHS) g_pcnt[i] = 0.0f;
}

__global__ void k_count(const int* __restrict__ dst, int E) {
    int e = blockIdx.x * blockDim.x + threadIdx.x;
    if (e < E) atomicAdd(&g_cnt[dst[e]], 1);
}

// Phase A: per-block exclusive scan of g_cnt -> g_rowptr (local), block totals
// to g_bsum. Also computes dinv (reads g_cnt anyway).
__global__ void k_scanA(int n) {
    __shared__ int swarp[32];
    int t = threadIdx.x;            // 1024
    int i = blockIdx.x * SCAN_B + t;
    int lane = t & 31, wid = t >> 5;
    int v = (i < n) ? g_cnt[i] : 0;
    if (i < n) g_dinv[i] = rsqrtf((float)v + 1.0f);
    int incl = v;
#pragma unroll
    for (int off = 1; off < 32; off <<= 1) {
        int y = __shfl_up_sync(0xffffffffu, incl, off);
        if (lane >= off) incl += y;
    }
    if (lane == 31) swarp[wid] = incl;
    __syncthreads();
    if (wid == 0) {
        int w = swarp[lane];
#pragma unroll
        for (int off = 1; off < 32; off <<= 1) {
            int y = __shfl_up_sync(0xffffffffu, w, off);
            if (lane >= off) w += y;
        }
        swarp[lane] = w;
    }
    __syncthreads();
    int excl = incl - v + ((wid > 0) ? swarp[wid - 1] : 0);
    if (i < n) g_rowptr[i] = excl;
    if (t == SCAN_B - 1) g_bsum[blockIdx.x] = excl + v;
}

// Phase B: single block scans the <=64 block totals in-place (exclusive).
__global__ void k_scanB(int nb) {
    __shared__ int swarp[32];
    int t = threadIdx.x;            // 1024 (only first nb matter)
    int lane = t & 31, wid = t >> 5;
    int v = (t < nb) ? g_bsum[t] : 0;
    int incl = v;
#pragma unroll
    for (int off = 1; off < 32; off <<= 1) {
        int y = __shfl_up_sync(0xffffffffu, incl, off);
        if (lane >= off) incl += y;
    }
    if (lane == 31) swarp[wid] = incl;
    __syncthreads();
    if (wid == 0) {
        int w = swarp[lane];
#pragma unroll
        for (int off = 1; off < 32; off <<= 1) {
            int y = __shfl_up_sync(0xffffffffu, w, off);
            if (lane >= off) w += y;
        }
        swarp[lane] = w;
    }
    __syncthreads();
    int excl = incl - v + ((wid > 0) ? swarp[wid - 1] : 0);
    if (t < nb) g_bsum[t] = excl;
}

// Phase C: add block offsets; zero cursor; finalize rowptr[n].
__global__ void k_scanC(int n, int E) {
    int i = blockIdx.x * blockDim.x + threadIdx.x;
    if (i < n) {
        g_rowptr[i] += g_bsum[i >> 10];
        g_cursor[i] = 0;
    }
    if (i == 0) g_rowptr[n] = E;
}

__global__ void k_fill(const int* __restrict__ src, const int* __restrict__ dst, int E) {
    int e = blockIdx.x * blockDim.x + threadIdx.x;
    if (e < E) {
        int s = src[e], d = dst[e];
        int pos = g_rowptr[d] + atomicAdd(&g_cursor[d], 1);
        g_esrc[pos] = s;
        g_enorm[pos] = g_dinv[s] * g_dinv[d];
    }
}

// ---------------- aggregation (pull, CSR) ----------------
// C=3 special: thread per node
__global__ void k_agg3(const float* __restrict__ x, int n) {
    int i = blockIdx.x * blockDim.x + threadIdx.x;
    if (i >= n) return;
    int beg = g_rowptr[i], end = g_rowptr[i + 1];
    float di = g_dinv[i];
    float w0 = di * di;
    float a0 = x[i * 3 + 0] * w0, a1 = x[i * 3 + 1] * w0, a2 = x[i * 3 + 2] * w0;
    for (int j = beg; j < end; j++) {
        int s = g_esrc[j];
        float w = g_enorm[j];
        a0 += x[s * 3 + 0] * w;
        a1 += x[s * 3 + 1] * w;
        a2 += x[s * 3 + 2] * w;
    }
    g_a[i * 3 + 0] = a0; g_a[i * 3 + 1] = a1; g_a[i * 3 + 2] = a2;
}

// warp per node; VPL floats per lane (C = 32*VPL), vectorized loads
template <int VPL>
__global__ void k_agg(int n) {
    const int C = 32 * VPL;
    int warp = (blockIdx.x * blockDim.x + threadIdx.x) >> 5;
    int lane = threadIdx.x & 31;
    if (warp >= n) return;
    int i = warp;
    int beg = g_rowptr[i], end = g_rowptr[i + 1];
    float di = g_dinv[i];
    float sw = di * di;
    float acc[VPL];
    const float* __restrict__ hp = g_h;
#pragma unroll
    for (int v = 0; v < VPL; v++) acc[v] = hp[i * C + lane * VPL + v] * sw;

    int j = beg;
    for (; j + 4 <= end; j += 4) {
        int s0 = g_esrc[j], s1 = g_esrc[j + 1], s2 = g_esrc[j + 2], s3 = g_esrc[j + 3];
        float w0 = g_enorm[j], w1 = g_enorm[j + 1], w2 = g_enorm[j + 2], w3 = g_enorm[j + 3];
        if (VPL == 4) {
            float4 v0 = *(const float4*)&hp[s0 * C + lane * 4];
            float4 v1 = *(const float4*)&hp[s1 * C + lane * 4];
            float4 v2 = *(const float4*)&hp[s2 * C + lane * 4];
            float4 v3 = *(const float4*)&hp[s3 * C + lane * 4];
            acc[0] += v0.x * w0 + v1.x * w1 + v2.x * w2 + v3.x * w3;
            acc[1] += v0.y * w0 + v1.y * w1 + v2.y * w2 + v3.y * w3;
            acc[2] += v0.z * w0 + v1.z * w1 + v2.z * w2 + v3.z * w3;
            acc[3] += v0.w * w0 + v1.w * w1 + v2.w * w2 + v3.w * w3;
        } else {
            float2 v0 = *(const float2*)&hp[s0 * C + lane * 2];
            float2 v1 = *(const float2*)&hp[s1 * C + lane * 2];
            float2 v2 = *(const float2*)&hp[s2 * C + lane * 2];
            float2 v3 = *(const float2*)&hp[s3 * C + lane * 2];
            acc[0] += v0.x * w0 + v1.x * w1 + v2.x * w2 + v3.x * w3;
            acc[1] += v0.y * w0 + v1.y * w1 + v2.y * w2 + v3.y * w3;
        }
    }
    for (; j < end; j++) {
        int s = g_esrc[j];
        float w = g_enorm[j];
        if (VPL == 4) {
            float4 v = *(const float4*)&hp[s * C + lane * 4];
            acc[0] += v.x * w; acc[1] += v.y * w; acc[2] += v.z * w; acc[3] += v.w * w;
        } else {
            float2 v = *(const float2*)&hp[s * C + lane * 2];
            acc[0] += v.x * w; acc[1] += v.y * w;
        }
    }
    if (VPL == 4) {
        float4 o; o.x = acc[0]; o.y = acc[1]; o.z = acc[2]; o.w = acc[3];
        *(float4*)&g_a[i * C + lane * 4] = o;
    } else {
        float2 o; o.x = acc[0]; o.y = acc[1];
        *(float2*)&g_a[i * C + lane * 2] = o;
    }
}

// ---------------- GEMM + bias + relu:  g_h = relu(g_a @ W + b) ----------------
// K=3 special (layer 1): one thread per output element
__global__ void k_gemm3(const float* __restrict__ W, const float* __restrict__ b, int n) {
    int idx = blockIdx.x * blockDim.x + threadIdx.x;
    if (idx >= n * 64) return;
    int row = idx >> 6, c = idx & 63;
    float a0 = g_a[row * 3 + 0], a1 = g_a[row * 3 + 1], a2 = g_a[row * 3 + 2];
    float acc = b[c] + a0 * W[c] + a1 * W[64 + c] + a2 * W[128 + c];
    g_h[row * 64 + c] = fmaxf(acc, 0.0f);
}

// K in {64,128}, C=128. Block: dim3(64,2) = 128 thr. 16 rows/block,
// each thread: 8 rows x 2 channels, f32x2 accumulators.
template <int K>
__global__ void k_gemm(const float* __restrict__ W, const float* __restrict__ b, int n) {
    const int C = 128, ROWS = 16, RPT = 8;
    __shared__ float sh[ROWS][K];
    int tc = threadIdx.x;            // 0..63 -> channels 2tc, 2tc+1
    int ty = threadIdx.y;            // 0..1
    int tid = ty * 64 + tc;
    int row0 = blockIdx.x * ROWS;

    const int NV = ROWS * K / 4;
    for (int v = tid; v < NV; v += 128) {
        int o = v * 4;
        int r = o / K, k = o - r * K;
        int row = row0 + r;
        float4 val = (row < n) ? *(const float4*)&g_a[row * K + k]
                               : make_float4(0.f, 0.f, 0.f, 0.f);
        *(float4*)&sh[r][k] = val;
    }
    __syncthreads();

    const ull* __restrict__ Wll = (const ull*)W;
    ull acc[RPT];
    {
        float2 bb = *(const float2*)&b[2 * tc];
        ull binit = pack2(bb.x, bb.y);
#pragma unroll
        for (int r = 0; r < RPT; r++) acc[r] = binit;
    }
    int rbase = ty * RPT;
#pragma unroll 4
    for (int k = 0; k < K; k += 2) {
        ull w0 = Wll[k * (C / 2) + tc];
        ull w1 = Wll[(k + 1) * (C / 2) + tc];
#pragma unroll
        for (int r = 0; r < RPT; r++) {
            float2 s2 = *(const float2*)&sh[rbase + r][k];
            acc[r] = ffma2(pack2(s2.x, s2.x), w0, acc[r]);
            acc[r] = ffma2(pack2(s2.y, s2.y), w1, acc[r]);
        }
    }
#pragma unroll
    for (int r = 0; r < RPT; r++) {
        int row = row0 + rbase + r;
        if (row < n) {
            float x, y; unpack2(acc[r], x, y);
            float2 o; o.x = fmaxf(x, 0.0f); o.y = fmaxf(y, 0.0f);
            *(float2*)&g_h[row * C + 2 * tc] = o;
        }
    }
}

// ---------------- mean pool over sorted batch ----------------
__global__ void k_pool(const int* __restrict__ batch, int n) {
    const int NPB = 256;
    int c = threadIdx.x;  // 128 threads
    int i0 = blockIdx.x * NPB;
    int cur = -1, cnt = 0;
    float acc = 0.0f;
    for (int j = 0; j < NPB; j++) {
        int i = i0 + j;
        if (i >= n) break;
        int g = __ldg(&batch[i]);
        if (g != cur) {
            if (cur >= 0) {
                atomicAdd(&g_psum[cur * 128 + c], acc);
                if (c == 0) atomicAdd(&g_pcnt[cur], (float)cnt);
            }
            cur = g; acc = 0.0f; cnt = 0;
        }
        acc += g_h[i * 128 + c];
        cnt++;
    }
    if (cur >= 0) {
        atomicAdd(&g_psum[cur * 128 + c], acc);
        if (c == 0) atomicAdd(&g_pcnt[cur], (float)cnt);
    }
}

// ---------------- MLP head ----------------
__global__ void k_fc(const float* __restrict__ Wf1, const float* __restrict__ bf1,
                     const float* __restrict__ Wf2, const float* __restrict__ bf2,
                     float* __restrict__ out) {
    int g = blockIdx.x;
    int t = threadIdx.x;  // 128
    __shared__ float p[128];
    __shared__ float f1[64];
    float inv = 1.0f / fmaxf(g_pcnt[g], 1.0f);
    p[t] = g_psum[g * 128 + t] * inv;
    __syncthreads();
    if (t < 64) {
        float acc = bf1[t];
#pragma unroll
        for (int k = 0; k < 128; k++) acc += p[k] * Wf1[k * 64 + t];
        f1[t] = fmaxf(acc, 0.0f);
    }
    __syncthreads();
    if (t < 10) {
        float acc = bf2[t];
#pragma unroll
        for (int k = 0; k < 64; k++) acc += f1[k] * Wf2[k * 10 + t];
        out[g * 10 + t] = acc;
    }
}

extern "C" void kernel_launch(void* const* d_in, const int* in_sizes, int n_in,
                              void* d_out, int out_size) {
    const float* x   = (const float*)d_in[0];
    const int* ei    = (const int*)d_in[1];
    const int* batch = (const int*)d_in[2];
    const float* W1  = (const float*)d_in[3];
    const float* b1  = (const float*)d_in[4];
    const float* W2  = (const float*)d_in[5];
    const float* b2  = (const float*)d_in[6];
    const float* W3  = (const float*)d_in[7];
    const float* b3  = (const float*)d_in[8];
    const float* Wf1 = (const float*)d_in[9];
    const float* bf1 = (const float*)d_in[10];
    const float* Wf2 = (const float*)d_in[11];
    const float* bf2 = (const float*)d_in[12];
    float* out = (float*)d_out;

    int N = in_sizes[0] / 3;
    int E = in_sizes[1] / 2;
    const int* src = ei;
    const int* dst = ei + E;
    int NB = (N + SCAN_B - 1) / SCAN_B;

    // CSR + norms (once per launch, reused by all 3 layers)
    k_zero<<<(N + 255) / 256, 256>>>(N);
    k_count<<<(E + 255) / 256, 256>>>(dst, E);
    k_scanA<<<NB, SCAN_B>>>(N);
    k_scanB<<<1, SCAN_B>>>(NB);
    k_scanC<<<(N + 255) / 256, 256>>>(N, E);
    k_fill<<<(E + 255) / 256, 256>>>(src, dst, E);

    // Layer 1: aggregate at C=3, then 3->64 transform
    k_agg3<<<(N + 127) / 128, 128>>>(x, N);
    k_gemm3<<<(N * 64 + 255) / 256, 256>>>(W1, b1, N);

    // Layer 2: aggregate at C=64, then 64->128
    k_agg<2><<<(N + 7) / 8, 256>>>(N);
    k_gemm<64><<<(N + 15) / 16, dim3(64, 2)>>>(W2, b2, N);

    // Layer 3: aggregate at C=128, then 128->128
    k_agg<4><<<(N + 7) / 8, 256>>>(N);
    k_gemm<128><<<(N + 15) / 16, dim3(64, 2)>>>(W3, b3, N);

    // Pool + head
    k_pool<<<(N + 255) / 256, 128>>>(batch, N);
    k_fc<<<GRAPHS, 128>>>(Wf1, bf1, Wf2, bf2, out);
}